// round 11
// baseline (speedup 1.0000x reference)
#include <cuda_runtime.h>
#include <cstdint>

#define N_NODES 100000
#define DIN 128
#define HID 128
#define DOUT 64
#define MAX_E 1700000

// ---------------- scratch (no allocations; referenced ONLY from device code) -------
__device__ float g_norm_src[N_NODES];
__device__ float g_norm_dst[N_NODES];
__device__ float g_h[N_NODES * HID];    // GEMM output / scatter input
__device__ float g_m[N_NODES * HID];    // scatter accumulator
__device__ float g_act[N_NODES * HID];  // layer activations
__device__ int   g_src32[MAX_E];        // canonical int32 edge indices
__device__ int   g_dst32[MAX_E];
__device__ int   g_is64;                // 1 if input indices are int64-encoded

// ---------------- kernels ----------------

// Detect index width: treat raw buffer as int32 words. If indices are int64
// (values < 2^31), every odd word is 0. If int32, odd words are random node ids.
__global__ void detect_kernel(const int* __restrict__ raw, int E) {
    __shared__ int sOr[256];
    int acc = 0;
    int nsamp = E < 8192 ? E : 8192;
    for (int i = threadIdx.x; i < nsamp; i += 256)
        acc |= raw[2 * i + 1];  // safe for both widths: 2*i+1 < 2E words
    sOr[threadIdx.x] = acc;
    __syncthreads();
    for (int s = 128; s > 0; s >>= 1) {
        if (threadIdx.x < s) sOr[threadIdx.x] |= sOr[threadIdx.x + s];
        __syncthreads();
    }
    if (threadIdx.x == 0) g_is64 = (sOr[0] == 0) ? 1 : 0;
}

// Repack src/dst to int32, branching on detected width.
__global__ void repack_kernel(const int* __restrict__ srcraw,
                              const int* __restrict__ dstraw, int E) {
    int i = blockIdx.x * blockDim.x + threadIdx.x;
    if (i >= E) return;
    int stride64 = g_is64;  // 0 or 1
    int idx = i << stride64;  // i*2 if int64 (little-endian low word), else i
    g_src32[i] = srcraw[idx];
    g_dst32[i] = dstraw[idx];
}

// zero g_m (as float4) + g_norm_src/g_norm_dst in one pass
__global__ void setup_zero_kernel() {
    int i = blockIdx.x * blockDim.x + threadIdx.x;
    if (i < N_NODES * HID / 4)
        reinterpret_cast<float4*>(g_m)[i] = make_float4(0.f, 0.f, 0.f, 0.f);
    if (i < N_NODES) { g_norm_src[i] = 0.0f; g_norm_dst[i] = 0.0f; }
}

// 2 edges per thread: half the grid, same atomic count.
__global__ void deg_kernel(int E) {
    int i = (blockIdx.x * blockDim.x + threadIdx.x) * 2;
#pragma unroll
    for (int k = 0; k < 2; k++) {
        int e = i + k;
        if (e < E) {
            atomicAdd(&g_norm_src[g_src32[e]], 1.0f);
            atomicAdd(&g_norm_dst[g_dst32[e]], 1.0f);
        }
    }
}

__global__ void norm_kernel() {
    int i = blockIdx.x * blockDim.x + threadIdx.x;
    if (i < N_NODES) {
        g_norm_src[i] = rsqrtf(fmaxf(g_norm_src[i], 1.0f));
        g_norm_dst[i] = rsqrtf(fmaxf(g_norm_dst[i], 1.0f));
    }
}

// g_h[r, j] = sum_k (in[r,k] * g_norm_src[r]) * W[k, j]
// in = FROM_ACT ? g_act (device symbol) : x (harness pointer).
// block: KOUT threads (one output column each), 32 rows per block.
// Inner loop reads xs in float4 (LDS.128 broadcast) -> 1 LDS per 4 FFMAs.
template <int KIN, int KOUT, bool FROM_ACT>
__global__ void gemm_norm(const float* __restrict__ x, const float* __restrict__ W,
                          int n) {
    const float* __restrict__ in = FROM_ACT ? g_act : x;
    __shared__ __align__(16) float xs[32][KIN];
    int r0 = blockIdx.x * 32;
    int j = threadIdx.x;
    int nrows = n - r0;
    if (nrows > 32) nrows = 32;

    for (int idx = threadIdx.x; idx < nrows * KIN; idx += KOUT) {
        int r = idx / KIN, k = idx % KIN;
        xs[r][k] = in[(size_t)(r0 + r) * KIN + k] * g_norm_src[r0 + r];
    }
    __syncthreads();

    float acc[32];
#pragma unroll
    for (int r = 0; r < 32; r++) acc[r] = 0.0f;

    for (int k = 0; k < KIN; k += 4) {
        float w0 = W[(k + 0) * KOUT + j];
        float w1 = W[(k + 1) * KOUT + j];
        float w2 = W[(k + 2) * KOUT + j];
        float w3 = W[(k + 3) * KOUT + j];
#pragma unroll
        for (int r = 0; r < 32; r++) {
            float4 xv = *reinterpret_cast<const float4*>(&xs[r][k]);  // LDS.128 broadcast
            acc[r] += xv.x * w0 + xv.y * w1 + xv.z * w2 + xv.w * w3;
        }
    }

    for (int r = 0; r < nrows; r++) g_h[(size_t)(r0 + r) * KOUT + j] = acc[r];
}

// H=128: one warp per edge (32 float4s per row fills the warp exactly).
__global__ void scatter128_kernel(int E) {
    int wid = (blockIdx.x * blockDim.x + threadIdx.x) >> 5;
    int lane = threadIdx.x & 31;
    if (wid >= E) return;
    int s = g_src32[wid];
    int d = g_dst32[wid];
    float4 v = reinterpret_cast<const float4*>(g_h)[(size_t)s * 32 + lane];
    float* mp = g_m + (size_t)d * 128 + lane * 4;
    atomicAdd(mp + 0, v.x);
    atomicAdd(mp + 1, v.y);
    atomicAdd(mp + 2, v.z);
    atomicAdd(mp + 3, v.w);
}

// H=64: two edges per warp (16 float4s per row) so no lane sits idle.
__global__ void scatter64_kernel(int E) {
    int wid = (blockIdx.x * blockDim.x + threadIdx.x) >> 5;
    int lane = threadIdx.x & 31;
    int e = wid * 2 + (lane >> 4);  // lanes 0-15 -> edge0, 16-31 -> edge1
    int sub = lane & 15;
    if (e >= E) return;
    int s = g_src32[e];
    int d = g_dst32[e];
    float4 v = reinterpret_cast<const float4*>(g_h)[(size_t)s * 16 + sub];
    float* mp = g_m + (size_t)d * 64 + sub * 4;
    atomicAdd(mp + 0, v.x);
    atomicAdd(mp + 1, v.y);
    atomicAdd(mp + 2, v.z);
    atomicAdd(mp + 3, v.w);
}

// dst = relu?(g_m * g_norm_dst + b). TO_ACT ? writes g_act : writes out (harness ptr).
// ZERO_M: re-zero g_m for the next layer's scatter.
template <int H, bool RELU, bool ZERO_M, bool TO_ACT>
__global__ void epilogue_kernel(const float* __restrict__ b,
                                float* __restrict__ out, int n) {
    float* __restrict__ dstp = TO_ACT ? g_act : out;
    int i = blockIdx.x * blockDim.x + threadIdx.x;  // one float4 per thread
    constexpr int V = H / 4;
    if (i >= n * V) return;
    int r = i / V, c = i % V;
    float nd = g_norm_dst[r];
    float4 mv = reinterpret_cast<float4*>(g_m)[i];
    float4 bv = reinterpret_cast<const float4*>(b)[c];
    float4 o;
    o.x = mv.x * nd + bv.x;
    o.y = mv.y * nd + bv.y;
    o.z = mv.z * nd + bv.z;
    o.w = mv.w * nd + bv.w;
    if (RELU) {
        o.x = fmaxf(o.x, 0.f); o.y = fmaxf(o.y, 0.f);
        o.z = fmaxf(o.z, 0.f); o.w = fmaxf(o.w, 0.f);
    }
    reinterpret_cast<float4*>(dstp)[i] = o;
    if (ZERO_M) reinterpret_cast<float4*>(g_m)[i] = make_float4(0.f, 0.f, 0.f, 0.f);
}

// ---------------- launch (kernel launches ONLY; only harness pointers passed) -------

extern "C" void kernel_launch(void* const* d_in, const int* in_sizes, int n_in,
                              void* d_out, int out_size) {
    const float* x = (const float*)d_in[0];
    const int* srcraw = (const int*)d_in[1];
    const int* dstraw = (const int*)d_in[2];
    const float* W1 = (const float*)d_in[3];
    const float* b1 = (const float*)d_in[4];
    const float* W2 = (const float*)d_in[5];
    const float* b2 = (const float*)d_in[6];
    const float* W3 = (const float*)d_in[7];
    const float* b3 = (const float*)d_in[8];
    float* out = (float*)d_out;
    const int E = in_sizes[1];
    const int N = N_NODES;

    const int T = 256;
    auto cdiv = [](long long a, long long b) { return (int)((a + b - 1) / b); };

    // index-width detection + repack to int32, zero buffers, degrees -> norms
    detect_kernel<<<1, 256>>>(srcraw, E);
    repack_kernel<<<cdiv(E, T), T>>>(srcraw, dstraw, E);
    setup_zero_kernel<<<cdiv((long long)N * HID / 4, T), T>>>();
    deg_kernel<<<cdiv(cdiv(E, 2), T), T>>>(E);
    norm_kernel<<<cdiv(N, T), T>>>();

    const int s128_blocks = cdiv((long long)E * 32, T);
    const int s64_blocks = cdiv((long long)cdiv(E, 2) * 32, T);
    const int e128_blocks = cdiv((long long)N * HID / 4, T);
    const int e64_blocks = cdiv((long long)N * DOUT / 4, T);

    // ---- layer 1: x[N,128] -> g_act[N,128], relu (epilogue re-zeros g_m)
    gemm_norm<DIN, HID, false><<<cdiv(N, 32), HID>>>(x, W1, N);
    scatter128_kernel<<<s128_blocks, T>>>(E);
    epilogue_kernel<HID, true, true, true><<<e128_blocks, T>>>(b1, out, N);

    // ---- layer 2: g_act[N,128] -> g_act[N,128], relu (epilogue re-zeros g_m)
    gemm_norm<HID, HID, true><<<cdiv(N, 32), HID>>>(x, W2, N);
    scatter128_kernel<<<s128_blocks, T>>>(E);
    epilogue_kernel<HID, true, true, true><<<e128_blocks, T>>>(b2, out, N);

    // ---- layer 3: g_act[N,128] -> out[N,64], no relu
    gemm_norm<HID, DOUT, true><<<cdiv(N, 32), DOUT>>>(x, W3, N);
    scatter64_kernel<<<s64_blocks, T>>>(E);
    epilogue_kernel<DOUT, false, false, false><<<e64_blocks, T>>>(b3, out, N);
}

// round 12
// speedup vs baseline: 1.5958x; 1.5958x over previous
#include <cuda_runtime.h>
#include <cstdint>

#define N_NODES 100000
#define DIN 128
#define HID 128
#define DOUT 64
#define MAX_E 1700000

// ---------------- scratch (no allocations; referenced ONLY from device code) -------
__device__ float g_norm_src[N_NODES];
__device__ float g_norm_dst[N_NODES];
__device__ float g_h[N_NODES * HID];    // GEMM output / scatter input
__device__ float g_m[N_NODES * HID];    // scatter accumulator
__device__ float g_act[N_NODES * HID];  // layer activations
__device__ int   g_src32[MAX_E];        // canonical int32 edge indices
__device__ int   g_dst32[MAX_E];
__device__ int   g_is64;                // 1 if input indices are int64-encoded

// ---------------- kernels ----------------

// Detect index width: treat raw buffer as int32 words. If indices are int64
// (values < 2^31), every odd word is 0. If int32, odd words are random node ids.
__global__ void detect_kernel(const int* __restrict__ raw, int E) {
    __shared__ int sOr[256];
    int acc = 0;
    int nsamp = E < 8192 ? E : 8192;
    for (int i = threadIdx.x; i < nsamp; i += 256)
        acc |= raw[2 * i + 1];  // safe for both widths: 2*i+1 < 2E words
    sOr[threadIdx.x] = acc;
    __syncthreads();
    for (int s = 128; s > 0; s >>= 1) {
        if (threadIdx.x < s) sOr[threadIdx.x] |= sOr[threadIdx.x + s];
        __syncthreads();
    }
    if (threadIdx.x == 0) g_is64 = (sOr[0] == 0) ? 1 : 0;
}

// Repack src/dst to int32, branching on detected width.
__global__ void repack_kernel(const int* __restrict__ srcraw,
                              const int* __restrict__ dstraw, int E) {
    int i = blockIdx.x * blockDim.x + threadIdx.x;
    if (i >= E) return;
    int stride64 = g_is64;  // 0 or 1
    int idx = i << stride64;  // i*2 if int64 (little-endian low word), else i
    g_src32[i] = srcraw[idx];
    g_dst32[i] = dstraw[idx];
}

// zero g_m (as float4) + g_norm_src/g_norm_dst in one pass
__global__ void setup_zero_kernel() {
    int i = blockIdx.x * blockDim.x + threadIdx.x;
    if (i < N_NODES * HID / 4)
        reinterpret_cast<float4*>(g_m)[i] = make_float4(0.f, 0.f, 0.f, 0.f);
    if (i < N_NODES) { g_norm_src[i] = 0.0f; g_norm_dst[i] = 0.0f; }
}

// 2 edges per thread: half the grid, same atomic count.
__global__ void deg_kernel(int E) {
    int i = (blockIdx.x * blockDim.x + threadIdx.x) * 2;
#pragma unroll
    for (int k = 0; k < 2; k++) {
        int e = i + k;
        if (e < E) {
            atomicAdd(&g_norm_src[g_src32[e]], 1.0f);
            atomicAdd(&g_norm_dst[g_dst32[e]], 1.0f);
        }
    }
}

__global__ void norm_kernel() {
    int i = blockIdx.x * blockDim.x + threadIdx.x;
    if (i < N_NODES) {
        g_norm_src[i] = rsqrtf(fmaxf(g_norm_src[i], 1.0f));
        g_norm_dst[i] = rsqrtf(fmaxf(g_norm_dst[i], 1.0f));
    }
}

// g_h[r, j] = sum_k (in[r,k] * g_norm_src[r]) * W[k, j]
// in = FROM_ACT ? g_act (device symbol) : x (harness pointer).
// block: KOUT threads (one output column each), 32 rows per block.
// Inner loop reads xs in float4 (LDS.128 broadcast) -> 1 LDS per 4 FFMAs.
template <int KIN, int KOUT, bool FROM_ACT>
__global__ void gemm_norm(const float* __restrict__ x, const float* __restrict__ W,
                          int n) {
    const float* __restrict__ in = FROM_ACT ? g_act : x;
    __shared__ __align__(16) float xs[32][KIN];
    int r0 = blockIdx.x * 32;
    int j = threadIdx.x;
    int nrows = n - r0;
    if (nrows > 32) nrows = 32;

    for (int idx = threadIdx.x; idx < nrows * KIN; idx += KOUT) {
        int r = idx / KIN, k = idx % KIN;
        xs[r][k] = in[(size_t)(r0 + r) * KIN + k] * g_norm_src[r0 + r];
    }
    __syncthreads();

    float acc[32];
#pragma unroll
    for (int r = 0; r < 32; r++) acc[r] = 0.0f;

    for (int k = 0; k < KIN; k += 4) {
        float w0 = W[(k + 0) * KOUT + j];
        float w1 = W[(k + 1) * KOUT + j];
        float w2 = W[(k + 2) * KOUT + j];
        float w3 = W[(k + 3) * KOUT + j];
#pragma unroll
        for (int r = 0; r < 32; r++) {
            float4 xv = *reinterpret_cast<const float4*>(&xs[r][k]);  // LDS.128 broadcast
            acc[r] += xv.x * w0 + xv.y * w1 + xv.z * w2 + xv.w * w3;
        }
    }

    for (int r = 0; r < nrows; r++) g_h[(size_t)(r0 + r) * KOUT + j] = acc[r];
}

// Vector reduction: 1 instruction, one 16B L2 RMW (PTX 8.1+, sm_90+).
// (Rounds 4/5 err-717 is now attributed to the int64-index bug, not this op.)
__device__ __forceinline__ void red_add_v4(float* p, float4 v) {
    asm volatile("red.global.add.v4.f32 [%0], {%1, %2, %3, %4};"
                 :: "l"(p), "f"(v.x), "f"(v.y), "f"(v.z), "f"(v.w)
                 : "memory");
}

// H=128: one warp per edge (32 float4s per row fills the warp exactly).
__global__ void scatter128_kernel(int E) {
    int wid = (blockIdx.x * blockDim.x + threadIdx.x) >> 5;
    int lane = threadIdx.x & 31;
    if (wid >= E) return;
    int s = g_src32[wid];
    int d = g_dst32[wid];
    float4 v = reinterpret_cast<const float4*>(g_h)[(size_t)s * 32 + lane];
    red_add_v4(g_m + (size_t)d * 128 + lane * 4, v);
}

// H=64: two edges per warp (16 float4s per row) so no lane sits idle.
__global__ void scatter64_kernel(int E) {
    int wid = (blockIdx.x * blockDim.x + threadIdx.x) >> 5;
    int lane = threadIdx.x & 31;
    int e = wid * 2 + (lane >> 4);  // lanes 0-15 -> edge0, 16-31 -> edge1
    int sub = lane & 15;
    if (e >= E) return;
    int s = g_src32[e];
    int d = g_dst32[e];
    float4 v = reinterpret_cast<const float4*>(g_h)[(size_t)s * 16 + sub];
    red_add_v4(g_m + (size_t)d * 64 + sub * 4, v);
}

// dst = relu?(g_m * g_norm_dst + b). TO_ACT ? writes g_act : writes out (harness ptr).
// ZERO_M: re-zero g_m for the next layer's scatter.
template <int H, bool RELU, bool ZERO_M, bool TO_ACT>
__global__ void epilogue_kernel(const float* __restrict__ b,
                                float* __restrict__ out, int n) {
    float* __restrict__ dstp = TO_ACT ? g_act : out;
    int i = blockIdx.x * blockDim.x + threadIdx.x;  // one float4 per thread
    constexpr int V = H / 4;
    if (i >= n * V) return;
    int r = i / V, c = i % V;
    float nd = g_norm_dst[r];
    float4 mv = reinterpret_cast<float4*>(g_m)[i];
    float4 bv = reinterpret_cast<const float4*>(b)[c];
    float4 o;
    o.x = mv.x * nd + bv.x;
    o.y = mv.y * nd + bv.y;
    o.z = mv.z * nd + bv.z;
    o.w = mv.w * nd + bv.w;
    if (RELU) {
        o.x = fmaxf(o.x, 0.f); o.y = fmaxf(o.y, 0.f);
        o.z = fmaxf(o.z, 0.f); o.w = fmaxf(o.w, 0.f);
    }
    reinterpret_cast<float4*>(dstp)[i] = o;
    if (ZERO_M) reinterpret_cast<float4*>(g_m)[i] = make_float4(0.f, 0.f, 0.f, 0.f);
}

// ---------------- launch (kernel launches ONLY; only harness pointers passed) -------

extern "C" void kernel_launch(void* const* d_in, const int* in_sizes, int n_in,
                              void* d_out, int out_size) {
    const float* x = (const float*)d_in[0];
    const int* srcraw = (const int*)d_in[1];
    const int* dstraw = (const int*)d_in[2];
    const float* W1 = (const float*)d_in[3];
    const float* b1 = (const float*)d_in[4];
    const float* W2 = (const float*)d_in[5];
    const float* b2 = (const float*)d_in[6];
    const float* W3 = (const float*)d_in[7];
    const float* b3 = (const float*)d_in[8];
    float* out = (float*)d_out;
    const int E = in_sizes[1];
    const int N = N_NODES;

    const int T = 256;
    auto cdiv = [](long long a, long long b) { return (int)((a + b - 1) / b); };

    // index-width detection + repack to int32, zero buffers, degrees -> norms
    detect_kernel<<<1, 256>>>(srcraw, E);
    repack_kernel<<<cdiv(E, T), T>>>(srcraw, dstraw, E);
    setup_zero_kernel<<<cdiv((long long)N * HID / 4, T), T>>>();
    deg_kernel<<<cdiv(cdiv(E, 2), T), T>>>(E);
    norm_kernel<<<cdiv(N, T), T>>>();

    const int s128_blocks = cdiv((long long)E * 32, T);
    const int s64_blocks = cdiv((long long)cdiv(E, 2) * 32, T);
    const int e128_blocks = cdiv((long long)N * HID / 4, T);
    const int e64_blocks = cdiv((long long)N * DOUT / 4, T);

    // ---- layer 1: x[N,128] -> g_act[N,128], relu (epilogue re-zeros g_m)
    gemm_norm<DIN, HID, false><<<cdiv(N, 32), HID>>>(x, W1, N);
    scatter128_kernel<<<s128_blocks, T>>>(E);
    epilogue_kernel<HID, true, true, true><<<e128_blocks, T>>>(b1, out, N);

    // ---- layer 2: g_act[N,128] -> g_act[N,128], relu (epilogue re-zeros g_m)
    gemm_norm<HID, HID, true><<<cdiv(N, 32), HID>>>(x, W2, N);
    scatter128_kernel<<<s128_blocks, T>>>(E);
    epilogue_kernel<HID, true, true, true><<<e128_blocks, T>>>(b2, out, N);

    // ---- layer 3: g_act[N,128] -> out[N,64], no relu
    gemm_norm<HID, DOUT, true><<<cdiv(N, 32), DOUT>>>(x, W3, N);
    scatter64_kernel<<<s64_blocks, T>>>(E);
    epilogue_kernel<DOUT, false, false, false><<<e64_blocks, T>>>(b3, out, N);
}